// round 3
// baseline (speedup 1.0000x reference)
#include <cuda_runtime.h>
#include <cuda_bf16.h>

#define HID   128
#define NRAD  16
#define MAX_NODES 50000

__device__ float g_x[MAX_NODES * HID];

// ---------------------------------------------------------------------------
// f32x2 packed helpers (Blackwell FFMA2 path — ptxas never auto-emits this)
// ---------------------------------------------------------------------------
__device__ __forceinline__ unsigned long long ffma2(unsigned long long a,
                                                    unsigned long long b,
                                                    unsigned long long c) {
    unsigned long long d;
    asm("fma.rn.f32x2 %0, %1, %2, %3;" : "=l"(d) : "l"(a), "l"(b), "l"(c));
    return d;
}
__device__ __forceinline__ float f2sum(unsigned long long v) {
    float lo, hi;
    asm("mov.b64 {%0, %1}, %2;" : "=f"(lo), "=f"(hi) : "l"(v));
    return lo + hi;
}

// ---------------------------------------------------------------------------
// Kernel 0: zero accumulator
// ---------------------------------------------------------------------------
__global__ void zero_x_kernel(int n_nodes) {
    int n4 = n_nodes * HID / 4;
    float4* p = reinterpret_cast<float4*>(g_x);
    for (int i = blockIdx.x * blockDim.x + threadIdx.x; i < n4; i += gridDim.x * blockDim.x)
        p[i] = make_float4(0.f, 0.f, 0.f, 0.f);
}

// ---------------------------------------------------------------------------
// Kernel 1: fused edge pipeline (512 threads, 64-edge tiles, persistent)
//   phase1: hid = silu(rb @ rW1 + rb1)          [e][k] k-major in smem
//   phase2: W = hid @ rW2 + rb2 via FFMA2 k-pair decomposition
//   epilogue: gather h[src] (LDG.128), scatter red.global.add.v4.f32
// smem W2^T rows swizzled: word (k + 4j) & 127 -> conflict-free LDS.128
// ---------------------------------------------------------------------------
#define E_TILE 64
#define EO_W2T 0                     // 128*128 = 16384 floats (transposed+swizzled)
#define EO_HID 16384                 // 64*128  = 8192
#define EO_RW1 24576                 // 16*128  = 2048
#define EO_RB  26624                 // 64*16   = 1024
#define EO_IDX 27648                 // 128 ints
#define EDGE_SMEM_FLOATS (27648 + 128)
#define EDGE_SMEM_BYTES  (EDGE_SMEM_FLOATS * 4)

__global__ __launch_bounds__(512, 1)
void edge_kernel(const float* __restrict__ h,
                 const float* __restrict__ radial,
                 const int*   __restrict__ ei,
                 const float* __restrict__ rW1, const float* __restrict__ rb1,
                 const float* __restrict__ rW2, const float* __restrict__ rb2,
                 int n_edges)
{
    extern __shared__ float smem[];
    float* s_w2t = smem + EO_W2T;
    float* s_hid = smem + EO_HID;
    float* s_rw1 = smem + EO_RW1;
    float* s_rb  = smem + EO_RB;
    int*   s_src = reinterpret_cast<int*>(smem + EO_IDX);
    int*   s_dst = s_src + E_TILE;

    const int tid = threadIdx.x;

    // W2 transposed + row-swizzled: s_w2t[j*128 + ((k+4j)&127)] = rW2[k][j]
    for (int i = tid; i < HID * HID; i += 512) {
        int k = i >> 7, j = i & 127;
        s_w2t[j * 128 + ((k + 4 * j) & 127)] = rW2[i];
    }
    for (int i = tid; i < NRAD * HID; i += 512) s_rw1[i] = rW1[i];
    __syncthreads();

    // phase-1 identity
    const int j = tid & (HID - 1);
    const int q = tid >> 7;              // 0..3, 16 edges each
    float w1c[NRAD];
#pragma unroll
    for (int k = 0; k < NRAD; ++k) w1c[k] = s_rw1[k * HID + j];
    const float rb1j = rb1[j];

    // phase-2 identity
    const int jg = tid & 31;             // feature quad
    const int eg = tid >> 5;             // 0..15, edge quad
    const int j0 = jg * 4;
    const int e0l = eg * 4;
    const float4 rb2v = *(const float4*)(rb2 + j0);
    int rot[4];
#pragma unroll
    for (int p = 0; p < 4; ++p) rot[p] = (4 * (j0 + p)) & 127;

    const int n_tiles = (n_edges + E_TILE - 1) / E_TILE;

    for (int t = blockIdx.x; t < n_tiles; t += gridDim.x) {
        const int te0 = t * E_TILE;
        __syncthreads();

        // load radial tile (256 float4) + indices
        for (int i = tid; i < E_TILE * NRAD / 4; i += 512) {
            int e = te0 + (i >> 2);
            float4 v = make_float4(0.f, 0.f, 0.f, 0.f);
            if (e < n_edges) v = ((const float4*)(radial + (size_t)te0 * NRAD))[i];
            ((float4*)s_rb)[i] = v;
        }
        if (tid < E_TILE) {
            int e = te0 + tid;
            s_src[tid] = (e < n_edges) ? ei[e] : 0;
            s_dst[tid] = (e < n_edges) ? ei[n_edges + e] : 0;
        }
        __syncthreads();

        // Phase 1: hid[e][j] = silu(rb@rW1 + rb1)
        for (int e = q * 16; e < q * 16 + 16; ++e) {
            float a = rb1j;
            const float4* rbv = (const float4*)(s_rb + e * NRAD);
#pragma unroll
            for (int k4 = 0; k4 < 4; ++k4) {
                float4 r = rbv[k4];
                a = fmaf(r.x, w1c[4 * k4 + 0], a);
                a = fmaf(r.y, w1c[4 * k4 + 1], a);
                a = fmaf(r.z, w1c[4 * k4 + 2], a);
                a = fmaf(r.w, w1c[4 * k4 + 3], a);
            }
            float sg = 1.f / (1.f + __expf(-a));
            s_hid[e * HID + j] = a * sg;
        }
        __syncthreads();

        // Phase 2: 4j x 4e per thread, f32x2 k-pair accumulation
        unsigned long long acc[4][4];
#pragma unroll
        for (int a = 0; a < 4; ++a)
#pragma unroll
            for (int b = 0; b < 4; ++b) acc[a][b] = 0ULL;

        for (int kb = 0; kb < HID; kb += 4) {
            ulonglong2 wv[4], hv[4];
#pragma unroll
            for (int p = 0; p < 4; ++p)
                wv[p] = *(const ulonglong2*)(s_w2t + (j0 + p) * 128 + ((kb + rot[p]) & 127));
#pragma unroll
            for (int e2 = 0; e2 < 4; ++e2)
                hv[e2] = *(const ulonglong2*)(s_hid + (e0l + e2) * HID + kb);
#pragma unroll
            for (int p = 0; p < 4; ++p)
#pragma unroll
                for (int e2 = 0; e2 < 4; ++e2) {
                    acc[p][e2] = ffma2(wv[p].x, hv[e2].x, acc[p][e2]);
                    acc[p][e2] = ffma2(wv[p].y, hv[e2].y, acc[p][e2]);
                }
        }

        // Epilogue: gather-multiply-scatter (vectorized)
#pragma unroll
        for (int e2 = 0; e2 < 4; ++e2) {
            int e  = e0l + e2;
            int ge = te0 + e;
            if (ge < n_edges) {
                int sr = s_src[e];
                int ds = s_dst[e];
                float4 hv4 = *(const float4*)(h + (size_t)sr * HID + j0);
                float m0 = hv4.x * (f2sum(acc[0][e2]) + rb2v.x);
                float m1 = hv4.y * (f2sum(acc[1][e2]) + rb2v.y);
                float m2 = hv4.z * (f2sum(acc[2][e2]) + rb2v.z);
                float m3 = hv4.w * (f2sum(acc[3][e2]) + rb2v.w);
                float* dp = g_x + (size_t)ds * HID + j0;
                asm volatile("red.global.add.v4.f32 [%0], {%1, %2, %3, %4};"
                             :: "l"(dp), "f"(m0), "f"(m1), "f"(m2), "f"(m3) : "memory");
            }
        }
    }
}

// ---------------------------------------------------------------------------
// Kernel 2: node dense stack, same FFMA2 scheme; 3 transposed+swizzled W
// resident in smem. 256 threads, 32-node tiles.
// ---------------------------------------------------------------------------
#define N_TILE 32
#define NO_DWT 0                     // 3*16384 = 49152 floats
#define NO_X   49152                 // 32*128  = 4096
#define NO_OW  53248                 // 128
#define NODE_SMEM_FLOATS (53248 + 128)
#define NODE_SMEM_BYTES  (NODE_SMEM_FLOATS * 4)

__global__ __launch_bounds__(256, 1)
void node_kernel(const float* __restrict__ dW0, const float* __restrict__ db0,
                 const float* __restrict__ dW1, const float* __restrict__ db1,
                 const float* __restrict__ dW2, const float* __restrict__ db2,
                 const float* __restrict__ oW,  const float* __restrict__ ob,
                 float* __restrict__ out, int n_nodes)
{
    extern __shared__ float smem[];
    float* s_dwt = smem + NO_DWT;
    float* s_x   = smem + NO_X;
    float* s_oW  = smem + NO_OW;

    const int tid  = threadIdx.x;
    const int lane = tid & 31;
    const int warp = tid >> 5;

    // transpose + swizzle all three weight matrices
    const float* Ws[3] = { dW0, dW1, dW2 };
    for (int l = 0; l < 3; ++l) {
        const float* W = Ws[l];
        float* dstw = s_dwt + l * HID * HID;
        for (int i = tid; i < HID * HID; i += 256) {
            int k = i >> 7, jj = i & 127;
            dstw[jj * 128 + ((k + 4 * jj) & 127)] = W[i];
        }
    }
    if (tid < HID) s_oW[tid] = oW[tid];

    const int jg = tid & 31;     // feature quad id
    const int ng = tid >> 5;     // node quad id (0..7)
    const int j0 = jg * 4;
    const int nb = ng * 4;
    int rot[4];
#pragma unroll
    for (int p = 0; p < 4; ++p) rot[p] = (4 * (j0 + p)) & 127;

    float4 dbv[3];
    dbv[0] = *(const float4*)(db0 + j0);
    dbv[1] = *(const float4*)(db1 + j0);
    dbv[2] = *(const float4*)(db2 + j0);
    const float obv = ob[0];
    __syncthreads();

    const int n_tiles = (n_nodes + N_TILE - 1) / N_TILE;

    for (int t = blockIdx.x; t < n_tiles; t += gridDim.x) {
        const int n0 = t * N_TILE;
        __syncthreads();
        for (int i = tid; i < N_TILE * HID / 4; i += 256) {
            int n = n0 + (i >> 5);
            float4 v = make_float4(0.f, 0.f, 0.f, 0.f);
            if (n < n_nodes) v = ((const float4*)(g_x + (size_t)n0 * HID))[i];
            ((float4*)s_x)[i] = v;
        }
        __syncthreads();

#pragma unroll 1
        for (int l = 0; l < 3; ++l) {
            const float* Wt = s_dwt + l * HID * HID;
            unsigned long long acc[4][4];
#pragma unroll
            for (int a = 0; a < 4; ++a)
#pragma unroll
                for (int b = 0; b < 4; ++b) acc[a][b] = 0ULL;

            for (int kb = 0; kb < HID; kb += 4) {
                ulonglong2 wv[4], xv[4];
#pragma unroll
                for (int p = 0; p < 4; ++p)
                    wv[p] = *(const ulonglong2*)(Wt + (j0 + p) * 128 + ((kb + rot[p]) & 127));
#pragma unroll
                for (int n2 = 0; n2 < 4; ++n2)
                    xv[n2] = *(const ulonglong2*)(s_x + (nb + n2) * HID + kb);
#pragma unroll
                for (int p = 0; p < 4; ++p)
#pragma unroll
                    for (int n2 = 0; n2 < 4; ++n2) {
                        acc[p][n2] = ffma2(wv[p].x, xv[n2].x, acc[p][n2]);
                        acc[p][n2] = ffma2(wv[p].y, xv[n2].y, acc[p][n2]);
                    }
            }
            __syncthreads();
#pragma unroll
            for (int n2 = 0; n2 < 4; ++n2) {
                float4 v;
                float a0 = f2sum(acc[0][n2]) + ((const float*)&dbv[l])[0];
                float a1 = f2sum(acc[1][n2]) + ((const float*)&dbv[l])[1];
                float a2 = f2sum(acc[2][n2]) + ((const float*)&dbv[l])[2];
                float a3 = f2sum(acc[3][n2]) + ((const float*)&dbv[l])[3];
                v.x = a0 / (1.f + __expf(-a0));
                v.y = a1 / (1.f + __expf(-a1));
                v.z = a2 / (1.f + __expf(-a2));
                v.w = a3 / (1.f + __expf(-a3));
                *(float4*)(s_x + (nb + n2) * HID + j0) = v;
            }
            __syncthreads();
        }

        // output head: 8 warps x 4 nodes, shuffle reduce
#pragma unroll
        for (int nn = 0; nn < 4; ++nn) {
            int n = warp * 4 + nn;
            const float* xr = s_x + n * HID;
            float p = xr[lane]      * s_oW[lane]
                    + xr[lane + 32] * s_oW[lane + 32]
                    + xr[lane + 64] * s_oW[lane + 64]
                    + xr[lane + 96] * s_oW[lane + 96];
#pragma unroll
            for (int off = 16; off > 0; off >>= 1)
                p += __shfl_down_sync(0xffffffffu, p, off);
            if (lane == 0 && (n0 + n) < n_nodes)
                out[n0 + n] = p + obv;
        }
    }
}

// ---------------------------------------------------------------------------
extern "C" void kernel_launch(void* const* d_in, const int* in_sizes, int n_in,
                              void* d_out, int out_size)
{
    const float* h      = (const float*)d_in[0];
    const float* radial = (const float*)d_in[1];
    const int*   ei     = (const int*)  d_in[2];
    const float* rW1 = (const float*)d_in[3];
    const float* rb1 = (const float*)d_in[4];
    const float* rW2 = (const float*)d_in[5];
    const float* rb2 = (const float*)d_in[6];
    const float* dW0 = (const float*)d_in[7];
    const float* db0 = (const float*)d_in[8];
    const float* dW1 = (const float*)d_in[9];
    const float* db1 = (const float*)d_in[10];
    const float* dW2 = (const float*)d_in[11];
    const float* db2 = (const float*)d_in[12];
    const float* oW  = (const float*)d_in[13];
    const float* ob  = (const float*)d_in[14];
    float* out = (float*)d_out;

    const int n_nodes = in_sizes[0] / HID;
    const int n_edges = in_sizes[1] / NRAD;

    cudaFuncSetAttribute(edge_kernel, cudaFuncAttributeMaxDynamicSharedMemorySize, EDGE_SMEM_BYTES);
    cudaFuncSetAttribute(node_kernel, cudaFuncAttributeMaxDynamicSharedMemorySize, NODE_SMEM_BYTES);

    zero_x_kernel<<<512, 256>>>(n_nodes);
    edge_kernel<<<148, 512, EDGE_SMEM_BYTES>>>(h, radial, ei, rW1, rb1, rW2, rb2, n_edges);
    node_kernel<<<148, 256, NODE_SMEM_BYTES>>>(dW0, db0, dW1, db1, dW2, db2, oW, ob, out, n_nodes);
}

// round 7
// speedup vs baseline: 2.2330x; 2.2330x over previous
#include <cuda_runtime.h>
#include <cuda_bf16.h>

#define HID   128
#define NRAD  16
#define MAX_NODES 50000

__device__ float g_x[MAX_NODES * HID];

// ---------------------------------------------------------------------------
// Kernel 1: fused edge pipeline. 512 threads, E_TILE=128, persistent.
//   phase1: hid = silu(rb @ rW1 + rb1)            (s_hid [e][k], k-major)
//   phase2: W = hid @ rW2 + rb2; 4j x 8e register tile, kb=4 vector steps
//   epilogue: gather h[src] (LDG.128), scatter red.global.add.v4.f32
// Weight kept in ORIGINAL [k][j] layout: w-quad load s_w2[k*128 + 4*lane]
// is a conflict-free LDS.128; activation loads are warp-broadcast LDS.128.
// ---------------------------------------------------------------------------
#define E_TILE 128

#define EO_W2  0                      // 128*128 = 16384 floats
#define EO_HID 16384                  // 128*128 = 16384
#define EO_RW1 32768                  // 16*128  = 2048
#define EO_RB  34816                  // 128*16  = 2048
#define EO_IDX 36864                  // 256 ints
#define EDGE_SMEM_FLOATS (36864 + 256)
#define EDGE_SMEM_BYTES  (EDGE_SMEM_FLOATS * 4)   // ~148.5 KB

__global__ __launch_bounds__(512, 1)
void edge_kernel(const float* __restrict__ h,
                 const float* __restrict__ radial,
                 const int*   __restrict__ ei,
                 const float* __restrict__ rW1, const float* __restrict__ rb1,
                 const float* __restrict__ rW2, const float* __restrict__ rb2,
                 int n_edges)
{
    extern __shared__ float smem[];
    float* s_w2  = smem + EO_W2;    // [k][j] original layout
    float* s_hid = smem + EO_HID;   // [e][k]
    float* s_rw1 = smem + EO_RW1;   // [k][j]
    float* s_rb  = smem + EO_RB;    // [e][k]
    int*   s_src = reinterpret_cast<int*>(smem + EO_IDX);
    int*   s_dst = s_src + E_TILE;

    const int tid  = threadIdx.x;
    const int lane = tid & 31;
    const int warp = tid >> 5;          // 0..15

    for (int i = tid; i < HID * HID; i += 512) s_w2[i] = rW2[i];
    for (int i = tid; i < NRAD * HID; i += 512) s_rw1[i] = rW1[i];
    __syncthreads();

    // phase-1 identity: j = tid&127, q = tid>>7 handles 32 edges
    const int j = tid & (HID - 1);
    const int q = tid >> 7;
    float w1c[NRAD];
#pragma unroll
    for (int k = 0; k < NRAD; ++k) w1c[k] = s_rw1[k * HID + j];
    const float rb1j = rb1[j];

    // phase-2 identity: warp -> 8 edges, lane -> feature quad j0
    const int j0  = lane * 4;
    const int e0l = warp * 8;
    const float4 rb2v = *(const float4*)(rb2 + j0);

    const int n_tiles = (n_edges + E_TILE - 1) / E_TILE;

    for (int t = blockIdx.x; t < n_tiles; t += gridDim.x) {
        const int te0 = t * E_TILE;
        __syncthreads();   // smem reuse fence

        // load radial tile (128*16 floats = 512 float4) + indices
        for (int i = tid; i < E_TILE * NRAD / 4; i += 512) {
            int e = te0 + (i >> 2);
            float4 v = make_float4(0.f, 0.f, 0.f, 0.f);
            if (e < n_edges) v = ((const float4*)(radial + (size_t)te0 * NRAD))[i];
            ((float4*)s_rb)[i] = v;
        }
        if (tid < E_TILE) {
            int e = te0 + tid;
            s_src[tid] = (e < n_edges) ? ei[e] : 0;
            s_dst[tid] = (e < n_edges) ? ei[n_edges + e] : 0;
        }
        __syncthreads();

        // Phase 1: hid[e][j] = silu(rb @ rW1 + rb1)
        for (int e = q * 32; e < q * 32 + 32; ++e) {
            float a = rb1j;
            const float4* rbv = (const float4*)(s_rb + e * NRAD);
#pragma unroll
            for (int k4 = 0; k4 < 4; ++k4) {
                float4 r = rbv[k4];
                a = fmaf(r.x, w1c[4 * k4 + 0], a);
                a = fmaf(r.y, w1c[4 * k4 + 1], a);
                a = fmaf(r.z, w1c[4 * k4 + 2], a);
                a = fmaf(r.w, w1c[4 * k4 + 3], a);
            }
            float sg = 1.f / (1.f + __expf(-a));
            s_hid[e * HID + j] = a * sg;
        }
        __syncthreads();

        // Phase 2: acc[j-quad][8 edges], k in blocks of 4
        float acc[4][8];
#pragma unroll
        for (int p = 0; p < 4; ++p)
#pragma unroll
            for (int r = 0; r < 8; ++r) acc[p][r] = 0.f;

#pragma unroll 2
        for (int kb = 0; kb < HID; kb += 4) {
            float4 he[8];
#pragma unroll
            for (int r = 0; r < 8; ++r)
                he[r] = *(const float4*)(s_hid + (e0l + r) * HID + kb);   // broadcast
#pragma unroll
            for (int i = 0; i < 4; ++i) {
                float4 w4 = *(const float4*)(s_w2 + (kb + i) * HID + j0); // conflict-free
                const float hk[8] = { ((const float*)&he[0])[i], ((const float*)&he[1])[i],
                                      ((const float*)&he[2])[i], ((const float*)&he[3])[i],
                                      ((const float*)&he[4])[i], ((const float*)&he[5])[i],
                                      ((const float*)&he[6])[i], ((const float*)&he[7])[i] };
#pragma unroll
                for (int r = 0; r < 8; ++r) {
                    acc[0][r] = fmaf(w4.x, hk[r], acc[0][r]);
                    acc[1][r] = fmaf(w4.y, hk[r], acc[1][r]);
                    acc[2][r] = fmaf(w4.z, hk[r], acc[2][r]);
                    acc[3][r] = fmaf(w4.w, hk[r], acc[3][r]);
                }
            }
        }

        // Epilogue: gather-multiply-scatter
#pragma unroll
        for (int r = 0; r < 8; ++r) {
            int e  = e0l + r;
            int ge = te0 + e;
            if (ge < n_edges) {
                int sr = s_src[e];
                int ds = s_dst[e];
                float4 hv4 = *(const float4*)(h + (size_t)sr * HID + j0);
                float m0 = hv4.x * (acc[0][r] + rb2v.x);
                float m1 = hv4.y * (acc[1][r] + rb2v.y);
                float m2 = hv4.z * (acc[2][r] + rb2v.z);
                float m3 = hv4.w * (acc[3][r] + rb2v.w);
                float* dp = g_x + (size_t)ds * HID + j0;
                asm volatile("red.global.add.v4.f32 [%0], {%1, %2, %3, %4};"
                             :: "l"(dp), "f"(m0), "f"(m1), "f"(m2), "f"(m3) : "memory");
            }
        }
    }
}

// ---------------------------------------------------------------------------
// Kernel 2: node dense stack. 256 threads, N_TILE=32, persistent.
// Same 4j x 4n register-tile scheme; weights in original [k][j] layout.
// ---------------------------------------------------------------------------
#define N_TILE 32
#define NO_DW  0                      // 3*16384 = 49152 floats
#define NO_X   49152                  // 32*128  = 4096
#define NO_OW  53248                  // 128
#define NODE_SMEM_FLOATS (53248 + 128)
#define NODE_SMEM_BYTES  (NODE_SMEM_FLOATS * 4)   // ~208.5 KB

__global__ __launch_bounds__(256, 1)
void node_kernel(const float* __restrict__ dW0, const float* __restrict__ db0,
                 const float* __restrict__ dW1, const float* __restrict__ db1,
                 const float* __restrict__ dW2, const float* __restrict__ db2,
                 const float* __restrict__ oW,  const float* __restrict__ ob,
                 float* __restrict__ out, int n_nodes)
{
    extern __shared__ float smem[];
    float* s_dW = smem + NO_DW;
    float* s_x  = smem + NO_X;    // [n][k]
    float* s_oW = smem + NO_OW;

    const int tid  = threadIdx.x;
    const int lane = tid & 31;
    const int warp = tid >> 5;      // 0..7

    for (int i = tid; i < HID * HID; i += 256) {
        s_dW[i]                 = dW0[i];
        s_dW[HID * HID + i]     = dW1[i];
        s_dW[2 * HID * HID + i] = dW2[i];
    }
    if (tid < HID) s_oW[tid] = oW[tid];

    const int j0 = lane * 4;        // feature quad
    const int nb = warp * 4;        // node quad
    float4 dbv[3];
    dbv[0] = *(const float4*)(db0 + j0);
    dbv[1] = *(const float4*)(db1 + j0);
    dbv[2] = *(const float4*)(db2 + j0);
    const float obv = ob[0];
    __syncthreads();

    const int n_tiles = (n_nodes + N_TILE - 1) / N_TILE;

    for (int t = blockIdx.x; t < n_tiles; t += gridDim.x) {
        const int n0 = t * N_TILE;
        __syncthreads();
        for (int i = tid; i < N_TILE * HID / 4; i += 256) {
            int n = n0 + (i >> 5);
            float4 v = make_float4(0.f, 0.f, 0.f, 0.f);
            if (n < n_nodes) v = ((const float4*)(g_x + (size_t)n0 * HID))[i];
            ((float4*)s_x)[i] = v;
        }
        __syncthreads();

#pragma unroll 1
        for (int l = 0; l < 3; ++l) {
            const float* W = s_dW + l * HID * HID;
            float acc[4][4];
#pragma unroll
            for (int p = 0; p < 4; ++p)
#pragma unroll
                for (int r = 0; r < 4; ++r) acc[p][r] = 0.f;

#pragma unroll 2
            for (int kb = 0; kb < HID; kb += 4) {
                float4 xe[4];
#pragma unroll
                for (int r = 0; r < 4; ++r)
                    xe[r] = *(const float4*)(s_x + (nb + r) * HID + kb);  // broadcast
#pragma unroll
                for (int i = 0; i < 4; ++i) {
                    float4 w4 = *(const float4*)(W + (kb + i) * HID + j0);
                    const float xk[4] = { ((const float*)&xe[0])[i], ((const float*)&xe[1])[i],
                                          ((const float*)&xe[2])[i], ((const float*)&xe[3])[i] };
#pragma unroll
                    for (int r = 0; r < 4; ++r) {
                        acc[0][r] = fmaf(w4.x, xk[r], acc[0][r]);
                        acc[1][r] = fmaf(w4.y, xk[r], acc[1][r]);
                        acc[2][r] = fmaf(w4.z, xk[r], acc[2][r]);
                        acc[3][r] = fmaf(w4.w, xk[r], acc[3][r]);
                    }
                }
            }
            __syncthreads();
#pragma unroll
            for (int r = 0; r < 4; ++r) {
                float a0 = acc[0][r] + ((const float*)&dbv[l])[0];
                float a1 = acc[1][r] + ((const float*)&dbv[l])[1];
                float a2 = acc[2][r] + ((const float*)&dbv[l])[2];
                float a3 = acc[3][r] + ((const float*)&dbv[l])[3];
                float4 v;
                v.x = a0 / (1.f + __expf(-a0));
                v.y = a1 / (1.f + __expf(-a1));
                v.z = a2 / (1.f + __expf(-a2));
                v.w = a3 / (1.f + __expf(-a3));
                *(float4*)(s_x + (nb + r) * HID + j0) = v;
            }
            __syncthreads();
        }

        // output head: 8 warps x 4 nodes, shuffle reduce over 128 feats
#pragma unroll
        for (int nn = 0; nn < 4; ++nn) {
            int n = warp * 4 + nn;
            const float* xr = s_x + n * HID;
            float p = xr[lane]      * s_oW[lane]
                    + xr[lane + 32] * s_oW[lane + 32]
                    + xr[lane + 64] * s_oW[lane + 64]
                    + xr[lane + 96] * s_oW[lane + 96];
#pragma unroll
            for (int off = 16; off > 0; off >>= 1)
                p += __shfl_down_sync(0xffffffffu, p, off);
            if (lane == 0 && (n0 + n) < n_nodes)
                out[n0 + n] = p + obv;
        }
    }
}

// ---------------------------------------------------------------------------
extern "C" void kernel_launch(void* const* d_in, const int* in_sizes, int n_in,
                              void* d_out, int out_size)
{
    const float* h      = (const float*)d_in[0];
    const float* radial = (const float*)d_in[1];
    const int*   ei     = (const int*)  d_in[2];
    const float* rW1 = (const float*)d_in[3];
    const float* rb1 = (const float*)d_in[4];
    const float* rW2 = (const float*)d_in[5];
    const float* rb2 = (const float*)d_in[6];
    const float* dW0 = (const float*)d_in[7];
    const float* db0 = (const float*)d_in[8];
    const float* dW1 = (const float*)d_in[9];
    const float* db1 = (const float*)d_in[10];
    const float* dW2 = (const float*)d_in[11];
    const float* db2 = (const float*)d_in[12];
    const float* oW  = (const float*)d_in[13];
    const float* ob  = (const float*)d_in[14];
    float* out = (float*)d_out;

    const int n_nodes = in_sizes[0] / HID;
    const int n_edges = in_sizes[1] / NRAD;

    cudaFuncSetAttribute(edge_kernel, cudaFuncAttributeMaxDynamicSharedMemorySize, EDGE_SMEM_BYTES);
    cudaFuncSetAttribute(node_kernel, cudaFuncAttributeMaxDynamicSharedMemorySize, NODE_SMEM_BYTES);

    // Zero accumulator via memset node (capture-legal, one fewer kernel launch).
    void* gx_ptr = nullptr;
    cudaGetSymbolAddress(&gx_ptr, g_x);
    cudaMemsetAsync(gx_ptr, 0, (size_t)n_nodes * HID * sizeof(float));

    edge_kernel<<<148, 512, EDGE_SMEM_BYTES>>>(h, radial, ei, rW1, rb1, rW2, rb2, n_edges);
    node_kernel<<<148, 256, NODE_SMEM_BYTES>>>(dW0, db0, dW1, db1, dW2, db2, oW, ob, out, n_nodes);
}